// round 16
// baseline (speedup 1.0000x reference)
#include <cuda_runtime.h>
#include <math.h>
#include <stdint.h>
#define NPATH 11
__device__ float g_hctp_cg[NPATH*125];
__device__ float g_wtf[(size_t)NPATH*64*64*64];   // tf32 w, fragment-ordered

// ---------------- helpers ----------------
__device__ __forceinline__ uint32_t f2tf(float f){
    uint32_t u; asm("cvt.rna.tf32.f32 %0, %1;" : "=r"(u) : "f"(f)); return u;
}
__device__ __forceinline__ void mma8(float* d, const uint32_t* a, const uint32_t* b){
    asm volatile("mma.sync.aligned.m16n8k8.row.col.f32.tf32.tf32.f32 "
        "{%0,%1,%2,%3},{%4,%5,%6,%7},{%8,%9},{%0,%1,%2,%3};\n"
        : "+f"(d[0]),"+f"(d[1]),"+f"(d[2]),"+f"(d[3])
        : "r"(a[0]),"r"(a[1]),"r"(a[2]),"r"(a[3]),"r"(b[0]),"r"(b[1]));
}

// ---------------- CG builder (fp64, VERIFIED rel_err ~1e-6) ----------------
__device__ __forceinline__ double d_fact(int n){ double f=1; for(int i=2;i<=n;i++) f*=i; return f; }
__device__ __forceinline__ double d_dfact(int n){ double o=1; for(int k=n;k>0;k-=2) o*=k; return o; }
__device__ __forceinline__ double d_gmom(int n){ return (n&1)?0.0:d_dfact(n-1); }
__device__ __forceinline__ int d_cidx(int L,int a,int b){ int t=L-a; return t*(t+1)/2+(t-b); }
__device__ __forceinline__ double d_getB(int l,int i,int m,const double B2[6][5]){
    if(l==0) return 1.0; if(l==1) return (i==m)?1.0:0.0; return B2[i][m]; }

__global__ void hctp_build_cg(){
    __shared__ double sGL[NPATH][15][15]; __shared__ double sV[NPATH][15][5];
    __shared__ double sR[NPATH][5][15];  __shared__ double sG[NPATH][5][5];
    const int t=threadIdx.x; if(t>=NPATH) return;
    const int L1t[NPATH]={0,0,0,1,1,1,1,2,2,2,2};
    const int L2t[NPATH]={0,1,2,0,1,1,2,0,1,2,2};
    const int L3t[NPATH]={0,1,2,1,0,2,1,2,1,0,2};
    const int l1=L1t[t],l2=L2t[t],l3=L3t[t];
    const int L=l1+l2, DL=(L+1)*(L+2)/2, d1=2*l1+1, d2=2*l2+1, d3=2*l3+1;
    double B2[6][5];
    for(int i=0;i<6;i++) for(int m=0;m<5;m++) B2[i][m]=0.0;
    { double s3=sqrt(3.0),s2=sqrt(2.0),s6=sqrt(6.0);
      double pp=(3.0+s3)/(6.0*s2), qq=(3.0-s3)/(6.0*s2), rr=1.0/s6;
      B2[1][0]=1.0; B2[2][1]=1.0; B2[4][3]=1.0;
      B2[0][2]=-rr; B2[3][2]=pp;  B2[5][2]=-qq;
      B2[0][4]=-rr; B2[3][4]=-qq; B2[5][4]=pp; }
    int ca[15],cb[15];
    { int n=0; for(int a=L;a>=0;a--) for(int b=L-a;b>=0;b--){ca[n]=a;cb[n]=b;n++;} }
    for(int i=0;i<DL;i++) for(int j=0;j<DL;j++){
        int aa=ca[i]+ca[j], bb=cb[i]+cb[j];
        int cc=(L-ca[i]-cb[i])+(L-ca[j]-cb[j]);
        sGL[t][i][j]=d_gmom(aa)*d_gmom(bb)*d_gmom(cc); }
    const int kr=(L-l3)/2, Dl=(l3+1)*(l3+2)/2;
    int la[6],lb[6];
    { int n=0; for(int a=l3;a>=0;a--) for(int b=l3-a;b>=0;b--){la[n]=a;lb[n]=b;n++;} }
    for(int i=0;i<DL;i++) for(int m=0;m<d3;m++) sV[t][i][m]=0.0;
    for(int j=0;j<Dl;j++) for(int p=0;p<=kr;p++) for(int q=0;q<=kr-p;q++){
        int r=kr-p-q; double coef=d_fact(kr)/(d_fact(p)*d_fact(q)*d_fact(r));
        int row=d_cidx(L,la[j]+2*p,lb[j]+2*q);
        for(int m=0;m<d3;m++) sV[t][row][m]+=coef*d_getB(l3,j,m,B2); }
    for(int m=0;m<d3;m++) for(int c=0;c<DL;c++){
        double s=0; for(int u=0;u<DL;u++) s+=sV[t][u][m]*sGL[t][u][c]; sR[t][m][c]=s; }
    for(int m=0;m<d3;m++) for(int m2=0;m2<d3;m2++){
        double s=0; for(int c=0;c<DL;c++) s+=sR[t][m][c]*sV[t][c][m2]; sG[t][m][m2]=s; }
    for(int c=0;c<d3;c++){
        int piv=c; double mx=fabs(sG[t][c][c]);
        for(int r=c+1;r<d3;r++){ double v=fabs(sG[t][r][c]); if(v>mx){mx=v;piv=r;} }
        if(piv!=c){ for(int q=0;q<d3;q++){double tp=sG[t][c][q];sG[t][c][q]=sG[t][piv][q];sG[t][piv][q]=tp;}
                    for(int q=0;q<DL;q++){double tp=sR[t][c][q];sR[t][c][q]=sR[t][piv][q];sR[t][piv][q]=tp;} }
        double inv=1.0/sG[t][c][c];
        for(int q=0;q<d3;q++) sG[t][c][q]*=inv;
        for(int q=0;q<DL;q++) sR[t][c][q]*=inv;
        for(int r=0;r<d3;r++){ if(r==c) continue; double f=sG[t][r][c]; if(f==0.0) continue;
            for(int q=0;q<d3;q++) sG[t][r][q]-=f*sG[t][c][q];
            for(int q=0;q<DL;q++) sR[t][r][q]-=f*sR[t][c][q]; } }
    const int D1c=(l1+1)*(l1+2)/2, D2c=(l2+1)*(l2+2)/2;
    int a1s[6],b1s[6],a2s[6],b2s[6];
    { int n=0; for(int a=l1;a>=0;a--) for(int b=l1-a;b>=0;b--){a1s[n]=a;b1s[n]=b;n++;} }
    { int n=0; for(int a=l2;a>=0;a--) for(int b=l2-a;b>=0;b--){a2s[n]=a;b2s[n]=b;n++;} }
    for(int m1=0;m1<d1;m1++) for(int m2=0;m2<d2;m2++){
        double tL[15]; for(int q=0;q<DL;q++) tL[q]=0.0;
        for(int i1=0;i1<D1c;i1++){ double bv1=d_getB(l1,i1,m1,B2); if(bv1==0.0) continue;
            for(int i2=0;i2<D2c;i2++){ double bv2=d_getB(l2,i2,m2,B2); if(bv2==0.0) continue;
                tL[d_cidx(L,a1s[i1]+a2s[i2],b1s[i1]+b2s[i2])]+=bv1*bv2; } }
        for(int k=0;k<d3;k++){ double s=0; for(int c=0;c<DL;c++) s+=sR[t][k][c]*tL[c];
            g_hctp_cg[t*125+(m1*d2+m2)*d3+k]=(float)s; } }
}

// ---------------- w -> tf32 fragment-ordered precompute ----------------
// g_wtf[p][i][s][o][t] pair: {w[p][o][i][s*8+t], w[p][o][i][s*8+t+4]}, t=0..3
__global__ void hctp_wprep(const float* __restrict__ w){
    const int i = blockIdx.x, p = blockIdx.y, t = threadIdx.x;
    const float* wp = w + ((size_t)p<<18);
    float* dst = g_wtf + ((size_t)p<<18) + (size_t)i*4096;
    for(int u=t; u<4096; u+=256){
        int half = u & 1, pr = u >> 1;
        int t4 = pr & 3, o = (pr>>2)&63, s = pr>>8;
        int j = s*8 + t4 + half*4;
        uint32_t v = f2tf(wp[(size_t)o*4096 + i*64 + j]);
        ((uint32_t*)dst)[u] = v;
    }
}

// ---------------- main per-path kernel: mma.sync tf32 ----------------
__host__ __device__ constexpr int cM(int NB,int D3){ return ((NB*D3+31)/32)*32; }
__host__ __device__ constexpr int smem_floats(int l1,int l2,int l3,int nb){
    int d1=2*l1+1, d2=2*l2+1, d3=2*l3+1;
    int M=cM(nb,d3);
    return 2*M*68 + nb*64*d2 + d1*d2*d3;
}

template<int L1,int L2,int L3,int P,int NB,int TPB,bool ACC>
__global__ void __launch_bounds__(256,1) tp_mma(
    const float* __restrict__ x1, const float* __restrict__ x2,
    float* __restrict__ out, int n)
{
    constexpr int D1=2*L1+1, D2=2*L2+1, D3=2*L3+1;
    constexpr int K0=(L3==0)?0:((L3==1)?1:4);
    constexpr int M = cM(NB,D3);
    constexpr int NBD3 = NB*D3;
    constexpr int CH1=64*D1, CH2=64*D2;
    constexpr int NWM = M/32, NWN = 8/NWM, NS = 64/NWN, NT = NS/8;
    constexpr int JC = 64/TPB;
    constexpr int KB = (D1*D2>=25 && D3>3) ? 3 : D3;
    constexpr int OZ=0;
    constexpr int OX2=2*M*68, OCG=OX2+NB*D2*64;

    extern __shared__ float sm[];
    const int t=threadIdx.x;
    const int B0=blockIdx.x*NB;

    for(int q=t;q<D1*D2*D3;q+=256) sm[OCG+q]=g_hctp_cg[P*125+q];
    for(int q=t;q<NB*D2*64;q+=256){ int b=q/(D2*64), r=q-b*(D2*64), nn=r>>6, j=r&63;
        sm[OX2+q]=(B0+b<n)?x2[(size_t)(B0+b)*CH2+j*D2+nn]:0.f; }
    for(int q=t;q<2*M*68;q+=256) sm[OZ+q]=0.f;   // zero both z buffers (pad rows)
    __syncthreads();   // staging visible before first produce (round-15 bug fix)

    const int lane=t&31, wid=t>>5;
    const int g=lane>>2, tid=lane&3;
    const int mw = wid % NWM, nw = wid / NWM;

    const int pb = t / TPB, part = t % TPB;
    const bool pvalid = pb < NB;
    const bool pload  = pvalid && (B0+pb < n);
    const float* x1g = x1 + (size_t)(B0 + (pvalid?pb:0))*CH1;

    // per-warp B-fragment base in g_wtf (fragment-ordered)
    const uint32_t* wfb = (const uint32_t*)g_wtf + ((size_t)P<<18)
                        + (nw*NS + g)*8 + tid*2;

    float acc[2][NT][4];
    for(int a=0;a<2;a++)
        for(int b=0;b<NT;b++)
            for(int c=0;c<4;c++) acc[a][b][c]=0.f;

    float a_cur[D1];
    #pragma unroll
    for(int m=0;m<D1;m++) a_cur[m] = pload ? x1g[m] : 0.f;

    for(int i=0;i<64;i++){
        float* zb = sm + OZ + (i&1)*M*68;

        // produce z rows: b-blocked, KB k-rows share each x2 read
        if(pvalid){
            const float* x2b = sm + OX2 + pb*(D2*64) + part*JC;
            #pragma unroll
            for(int k0=0;k0<D3;k0+=KB){
                float tt[KB][D2];
                #pragma unroll
                for(int kk=0;kk<KB;kk++){
                    if(k0+kk<D3){
                        #pragma unroll
                        for(int nn=0;nn<D2;nn++){
                            float s_=0.f;
                            #pragma unroll
                            for(int m=0;m<D1;m++) s_+=a_cur[m]*sm[OCG+(m*D2+nn)*D3+(k0+kk)];
                            tt[kk][nn]=s_;
                        }
                    }
                }
                #pragma unroll
                for(int c=0;c<JC/4;c++){
                    float4 z4[KB];
                    #pragma unroll
                    for(int kk=0;kk<KB;kk++) z4[kk]=make_float4(0.f,0.f,0.f,0.f);
                    #pragma unroll
                    for(int nn=0;nn<D2;nn++){
                        float4 xv=*(const float4*)(x2b + nn*64 + c*4);
                        #pragma unroll
                        for(int kk=0;kk<KB;kk++){
                            z4[kk].x+=tt[kk][nn]*xv.x; z4[kk].y+=tt[kk][nn]*xv.y;
                            z4[kk].z+=tt[kk][nn]*xv.z; z4[kk].w+=tt[kk][nn]*xv.w;
                        }
                    }
                    #pragma unroll
                    for(int kk=0;kk<KB;kk++){
                        if(k0+kk<D3){
                            uint4 u; u.x=f2tf(z4[kk].x); u.y=f2tf(z4[kk].y);
                            u.z=f2tf(z4[kk].z); u.w=f2tf(z4[kk].w);
                            *(uint4*)(zb + (pb*D3+k0+kk)*68 + part*JC + c*4) = u;
                        }
                    }
                }
            }
        }
        // prefetch next i's x1
        float a_nxt[D1];
        #pragma unroll
        for(int m=0;m<D1;m++) a_nxt[m] = (pload && i<63) ? x1g[(i+1)*D1+m] : 0.f;

        __syncthreads();   // single barrier: z(i) visible; buffers alternate

        // mma phase; B-fragments direct from g_wtf, pipelined one s ahead
        const uint32_t* zu = (const uint32_t*)zb;
        const uint32_t* wfi = wfb + (size_t)i*4096;
        uint2 bpre[NT];
        #pragma unroll
        for(int nt=0;nt<NT;nt++) bpre[nt] = *(const uint2*)(wfi + nt*64);
        #pragma unroll
        for(int s=0;s<8;s++){
            uint32_t bfr[NT][2];
            #pragma unroll
            for(int nt=0;nt<NT;nt++){ bfr[nt][0]=bpre[nt].x; bfr[nt][1]=bpre[nt].y; }
            if(s<7){
                #pragma unroll
                for(int nt=0;nt<NT;nt++) bpre[nt] = *(const uint2*)(wfi + (s+1)*512 + nt*64);
            }
            uint32_t afr[2][4];
            #pragma unroll
            for(int mt=0;mt<2;mt++){
                int r0 = mw*32 + mt*16 + g;
                const uint32_t* z0 = zu + r0*68 + s*8 + tid;
                const uint32_t* z1 = zu + (r0+8)*68 + s*8 + tid;
                afr[mt][0]=z0[0]; afr[mt][1]=z1[0]; afr[mt][2]=z0[4]; afr[mt][3]=z1[4];
            }
            #pragma unroll
            for(int mt=0;mt<2;mt++)
                #pragma unroll
                for(int nt=0;nt<NT;nt++)
                    mma8(acc[mt][nt], afr[mt], bfr[nt]);
        }
        #pragma unroll
        for(int m=0;m<D1;m++) a_cur[m]=a_nxt[m];
    }

    // epilogue: registers -> global
    #pragma unroll
    for(int mt=0;mt<2;mt++){
        #pragma unroll
        for(int rr=0;rr<2;rr++){
            int row = mw*32 + mt*16 + g + rr*8;
            if(row >= NBD3) continue;
            int b = row / D3, k = row - (row/D3)*D3;
            if(B0+b >= n) continue;
            float* ob = out + (size_t)(B0+b)*576 + K0 + k;
            #pragma unroll
            for(int nt=0;nt<NT;nt++){
                int o = nw*NS + nt*8 + 2*tid;
                float v0 = acc[mt][nt][rr*2+0];
                float v1 = acc[mt][nt][rr*2+1];
                if(ACC){ ob[o*9]+=v0; ob[(o+1)*9]+=v1; }
                else   { ob[o*9]=v0;  ob[(o+1)*9]=v1;  }
            }
        }
    }
}

// ---------------- launch (size-based operand identification) ----------------
extern "C" void kernel_launch(void* const* d_in, const int* in_sizes, int n_in,
                              void* d_out, int out_size){
    const long long WELEMS=(long long)NPATH*64*64*64;
    const float* w=nullptr;
    long long minOther=0x7fffffffffffLL;
    for(int i=0;i<n_in;i++) if((long long)in_sizes[i]==WELEMS && !w) w=(const float*)d_in[i];
    for(int i=0;i<n_in;i++){ if((const float*)d_in[i]==w) continue;
        if((long long)in_sizes[i]<minOther) minOther=in_sizes[i]; }
    const int nvec=(int)(minOther/64);
    const float* x1p[3]={nullptr,nullptr,nullptr};
    const float* x2p[3]={nullptr,nullptr,nullptr};
    for(int i=0;i<n_in;i++){
        const float* p=(const float*)d_in[i]; if(p==w) continue;
        long long sz=in_sizes[i];
        for(int l=0;l<3;l++) if(sz==(long long)nvec*64*(2*l+1)){
            if(!x1p[l]) x1p[l]=p; else x2p[l]=p; break; }
    }
    float* out=(float*)d_out;

    hctp_build_cg<<<1,32>>>();
    hctp_wprep<<<dim3(64,NPATH),256>>>(w);

#define LP(Pp,L1,L2,L3,NB,TPB,ACC) do{ \
    constexpr int smem=smem_floats(L1,L2,L3,NB)*4; \
    cudaFuncSetAttribute(tp_mma<L1,L2,L3,Pp,NB,TPB,ACC>, cudaFuncAttributeMaxDynamicSharedMemorySize, smem); \
    tp_mma<L1,L2,L3,Pp,NB,TPB,ACC><<<(nvec+NB-1)/NB,256,smem>>>(x1p[L1],x2p[L2],out,nvec); }while(0)

    LP(0, 0,0,0, 48, 4, false);
    LP(1, 0,1,1, 42, 4, false);
    LP(2, 0,2,2, 25, 8, false);
    LP(3, 1,0,1, 42, 4, true);
    LP(4, 1,1,0, 48, 4, true);
    LP(5, 1,1,2, 25, 8, true);
    LP(6, 1,2,1, 42, 4, true);
    LP(7, 2,0,2, 25, 8, true);
    LP(8, 2,1,1, 42, 4, true);
    LP(9, 2,2,0, 48, 4, true);
    LP(10,2,2,2, 25, 8, true);
#undef LP
}

// round 17
// speedup vs baseline: 1.2078x; 1.2078x over previous
#include <cuda_runtime.h>
#include <math.h>
#include <stdint.h>
#define NPATH 11
__device__ float g_hctp_cg[NPATH*125];
__device__ float g_wtf[(size_t)NPATH*64*64*64];   // tf32 w, fragment-ordered

// ---------------- helpers ----------------
__device__ __forceinline__ uint32_t f2tf(float f){
    uint32_t u; asm("cvt.rna.tf32.f32 %0, %1;" : "=r"(u) : "f"(f)); return u;
}
__device__ __forceinline__ void mma8(float* d, const uint32_t* a, const uint32_t* b){
    asm volatile("mma.sync.aligned.m16n8k8.row.col.f32.tf32.tf32.f32 "
        "{%0,%1,%2,%3},{%4,%5,%6,%7},{%8,%9},{%0,%1,%2,%3};\n"
        : "+f"(d[0]),"+f"(d[1]),"+f"(d[2]),"+f"(d[3])
        : "r"(a[0]),"r"(a[1]),"r"(a[2]),"r"(a[3]),"r"(b[0]),"r"(b[1]));
}

// ---------------- CG builder (fp64, VERIFIED rel_err ~1e-6) ----------------
__device__ __forceinline__ double d_fact(int n){ double f=1; for(int i=2;i<=n;i++) f*=i; return f; }
__device__ __forceinline__ double d_dfact(int n){ double o=1; for(int k=n;k>0;k-=2) o*=k; return o; }
__device__ __forceinline__ double d_gmom(int n){ return (n&1)?0.0:d_dfact(n-1); }
__device__ __forceinline__ int d_cidx(int L,int a,int b){ int t=L-a; return t*(t+1)/2+(t-b); }
__device__ __forceinline__ double d_getB(int l,int i,int m,const double B2[6][5]){
    if(l==0) return 1.0; if(l==1) return (i==m)?1.0:0.0; return B2[i][m]; }

__global__ void hctp_build_cg(){
    __shared__ double sGL[NPATH][15][15]; __shared__ double sV[NPATH][15][5];
    __shared__ double sR[NPATH][5][15];  __shared__ double sG[NPATH][5][5];
    const int t=threadIdx.x; if(t>=NPATH) return;
    const int L1t[NPATH]={0,0,0,1,1,1,1,2,2,2,2};
    const int L2t[NPATH]={0,1,2,0,1,1,2,0,1,2,2};
    const int L3t[NPATH]={0,1,2,1,0,2,1,2,1,0,2};
    const int l1=L1t[t],l2=L2t[t],l3=L3t[t];
    const int L=l1+l2, DL=(L+1)*(L+2)/2, d1=2*l1+1, d2=2*l2+1, d3=2*l3+1;
    double B2[6][5];
    for(int i=0;i<6;i++) for(int m=0;m<5;m++) B2[i][m]=0.0;
    { double s3=sqrt(3.0),s2=sqrt(2.0),s6=sqrt(6.0);
      double pp=(3.0+s3)/(6.0*s2), qq=(3.0-s3)/(6.0*s2), rr=1.0/s6;
      B2[1][0]=1.0; B2[2][1]=1.0; B2[4][3]=1.0;
      B2[0][2]=-rr; B2[3][2]=pp;  B2[5][2]=-qq;
      B2[0][4]=-rr; B2[3][4]=-qq; B2[5][4]=pp; }
    int ca[15],cb[15];
    { int n=0; for(int a=L;a>=0;a--) for(int b=L-a;b>=0;b--){ca[n]=a;cb[n]=b;n++;} }
    for(int i=0;i<DL;i++) for(int j=0;j<DL;j++){
        int aa=ca[i]+ca[j], bb=cb[i]+cb[j];
        int cc=(L-ca[i]-cb[i])+(L-ca[j]-cb[j]);
        sGL[t][i][j]=d_gmom(aa)*d_gmom(bb)*d_gmom(cc); }
    const int kr=(L-l3)/2, Dl=(l3+1)*(l3+2)/2;
    int la[6],lb[6];
    { int n=0; for(int a=l3;a>=0;a--) for(int b=l3-a;b>=0;b--){la[n]=a;lb[n]=b;n++;} }
    for(int i=0;i<DL;i++) for(int m=0;m<d3;m++) sV[t][i][m]=0.0;
    for(int j=0;j<Dl;j++) for(int p=0;p<=kr;p++) for(int q=0;q<=kr-p;q++){
        int r=kr-p-q; double coef=d_fact(kr)/(d_fact(p)*d_fact(q)*d_fact(r));
        int row=d_cidx(L,la[j]+2*p,lb[j]+2*q);
        for(int m=0;m<d3;m++) sV[t][row][m]+=coef*d_getB(l3,j,m,B2); }
    for(int m=0;m<d3;m++) for(int c=0;c<DL;c++){
        double s=0; for(int u=0;u<DL;u++) s+=sV[t][u][m]*sGL[t][u][c]; sR[t][m][c]=s; }
    for(int m=0;m<d3;m++) for(int m2=0;m2<d3;m2++){
        double s=0; for(int c=0;c<DL;c++) s+=sR[t][m][c]*sV[t][c][m2]; sG[t][m][m2]=s; }
    for(int c=0;c<d3;c++){
        int piv=c; double mx=fabs(sG[t][c][c]);
        for(int r=c+1;r<d3;r++){ double v=fabs(sG[t][r][c]); if(v>mx){mx=v;piv=r;} }
        if(piv!=c){ for(int q=0;q<d3;q++){double tp=sG[t][c][q];sG[t][c][q]=sG[t][piv][q];sG[t][piv][q]=tp;}
                    for(int q=0;q<DL;q++){double tp=sR[t][c][q];sR[t][c][q]=sR[t][piv][q];sR[t][piv][q]=tp;} }
        double inv=1.0/sG[t][c][c];
        for(int q=0;q<d3;q++) sG[t][c][q]*=inv;
        for(int q=0;q<DL;q++) sR[t][c][q]*=inv;
        for(int r=0;r<d3;r++){ if(r==c) continue; double f=sG[t][r][c]; if(f==0.0) continue;
            for(int q=0;q<d3;q++) sG[t][r][q]-=f*sG[t][c][q];
            for(int q=0;q<DL;q++) sR[t][r][q]-=f*sR[t][c][q]; } }
    const int D1c=(l1+1)*(l1+2)/2, D2c=(l2+1)*(l2+2)/2;
    int a1s[6],b1s[6],a2s[6],b2s[6];
    { int n=0; for(int a=l1;a>=0;a--) for(int b=l1-a;b>=0;b--){a1s[n]=a;b1s[n]=b;n++;} }
    { int n=0; for(int a=l2;a>=0;a--) for(int b=l2-a;b>=0;b--){a2s[n]=a;b2s[n]=b;n++;} }
    for(int m1=0;m1<d1;m1++) for(int m2=0;m2<d2;m2++){
        double tL[15]; for(int q=0;q<DL;q++) tL[q]=0.0;
        for(int i1=0;i1<D1c;i1++){ double bv1=d_getB(l1,i1,m1,B2); if(bv1==0.0) continue;
            for(int i2=0;i2<D2c;i2++){ double bv2=d_getB(l2,i2,m2,B2); if(bv2==0.0) continue;
                tL[d_cidx(L,a1s[i1]+a2s[i2],b1s[i1]+b2s[i2])]+=bv1*bv2; } }
        for(int k=0;k<d3;k++){ double s=0; for(int c=0;c<DL;c++) s+=sR[t][k][c]*tL[c];
            g_hctp_cg[t*125+(m1*d2+m2)*d3+k]=(float)s; } }
}

// ---------------- w -> tf32 fragment-ordered precompute ----------------
// g_wtf[p][i][s][o][t] pair: {w[p][o][i][s*8+t], w[p][o][i][s*8+t+4]}, t=0..3
__global__ void hctp_wprep(const float* __restrict__ w){
    const int i = blockIdx.x, p = blockIdx.y, t = threadIdx.x;
    const float* wp = w + ((size_t)p<<18);
    float* dst = g_wtf + ((size_t)p<<18) + (size_t)i*4096;
    for(int u=t; u<4096; u+=256){
        int half = u & 1, pr = u >> 1;
        int t4 = pr & 3, o = (pr>>2)&63, s = pr>>8;
        int j = s*8 + t4 + half*4;
        uint32_t v = f2tf(wp[(size_t)o*4096 + i*64 + j]);
        ((uint32_t*)dst)[u] = v;
    }
}

// ---------------- main per-path kernel: mma.sync tf32 ----------------
__host__ __device__ constexpr int cM(int NB,int D3){ return ((NB*D3+31)/32)*32; }
__host__ __device__ constexpr int smem_floats(int l1,int l2,int l3,int nb){
    int d1=2*l1+1, d2=2*l2+1, d3=2*l3+1;
    int M=cM(nb,d3);
    return 2*M*68 + nb*64*d2 + d1*d2*d3;
}

template<int L1,int L2,int L3,int P,int NB,int TPB,bool ACC>
__global__ void __launch_bounds__(256,2) tp_mma(
    const float* __restrict__ x1, const float* __restrict__ x2,
    float* __restrict__ out, int n)
{
    constexpr int D1=2*L1+1, D2=2*L2+1, D3=2*L3+1;
    constexpr int K0=(L3==0)?0:((L3==1)?1:4);
    constexpr int M = cM(NB,D3);
    constexpr int NBD3 = NB*D3;
    constexpr int CH1=64*D1, CH2=64*D2;
    constexpr int NWM = M/32, NWN = 8/NWM, NS = 64/NWN, NT = NS/8;
    constexpr int JC = 64/TPB;
    constexpr int KB = (D1*D2>=25 && D3>3) ? 3 : D3;
    constexpr int OZ=0;
    constexpr int OX2=2*M*68, OCG=OX2+NB*D2*64;

    extern __shared__ float sm[];
    const int t=threadIdx.x;
    const int B0=blockIdx.x*NB;

    for(int q=t;q<D1*D2*D3;q+=256) sm[OCG+q]=g_hctp_cg[P*125+q];
    for(int q=t;q<NB*D2*64;q+=256){ int b=q/(D2*64), r=q-b*(D2*64), nn=r>>6, j=r&63;
        sm[OX2+q]=(B0+b<n)?x2[(size_t)(B0+b)*CH2+j*D2+nn]:0.f; }
    for(int q=t;q<2*M*68;q+=256) sm[OZ+q]=0.f;   // zero both z buffers (pad rows)
    __syncthreads();   // staging visible before first produce

    const int lane=t&31, wid=t>>5;
    const int g=lane>>2, tid=lane&3;
    const int mw = wid % NWM, nw = wid / NWM;

    const int pb = t / TPB, part = t % TPB;
    const bool pvalid = pb < NB;
    const bool pload  = pvalid && (B0+pb < n);
    const float* x1g = x1 + (size_t)(B0 + (pvalid?pb:0))*CH1;

    // per-warp B-fragment base in g_wtf (fragment-ordered)
    const uint32_t* wfb = (const uint32_t*)g_wtf + ((size_t)P<<18)
                        + (nw*NS + g)*8 + tid*2;

    float acc[2][NT][4];
    for(int a=0;a<2;a++)
        for(int b=0;b<NT;b++)
            for(int c=0;c<4;c++) acc[a][b][c]=0.f;

    float a_cur[D1];
    #pragma unroll
    for(int m=0;m<D1;m++) a_cur[m] = pload ? x1g[m] : 0.f;

    for(int i=0;i<64;i++){
        float* zb = sm + OZ + (i&1)*M*68;

        // produce z rows: b-blocked, KB k-rows share each x2 read
        if(pvalid){
            const float* x2b = sm + OX2 + pb*(D2*64) + part*JC;
            #pragma unroll
            for(int k0=0;k0<D3;k0+=KB){
                float tt[KB][D2];
                #pragma unroll
                for(int kk=0;kk<KB;kk++){
                    if(k0+kk<D3){
                        #pragma unroll
                        for(int nn=0;nn<D2;nn++){
                            float s_=0.f;
                            #pragma unroll
                            for(int m=0;m<D1;m++) s_+=a_cur[m]*sm[OCG+(m*D2+nn)*D3+(k0+kk)];
                            tt[kk][nn]=s_;
                        }
                    }
                }
                #pragma unroll
                for(int c=0;c<JC/4;c++){
                    float4 z4[KB];
                    #pragma unroll
                    for(int kk=0;kk<KB;kk++) z4[kk]=make_float4(0.f,0.f,0.f,0.f);
                    #pragma unroll
                    for(int nn=0;nn<D2;nn++){
                        float4 xv=*(const float4*)(x2b + nn*64 + c*4);
                        #pragma unroll
                        for(int kk=0;kk<KB;kk++){
                            z4[kk].x+=tt[kk][nn]*xv.x; z4[kk].y+=tt[kk][nn]*xv.y;
                            z4[kk].z+=tt[kk][nn]*xv.z; z4[kk].w+=tt[kk][nn]*xv.w;
                        }
                    }
                    #pragma unroll
                    for(int kk=0;kk<KB;kk++){
                        if(k0+kk<D3){
                            uint4 u; u.x=f2tf(z4[kk].x); u.y=f2tf(z4[kk].y);
                            u.z=f2tf(z4[kk].z); u.w=f2tf(z4[kk].w);
                            *(uint4*)(zb + (pb*D3+k0+kk)*68 + part*JC + c*4) = u;
                        }
                    }
                }
            }
        }
        // prefetch next i's x1
        float a_nxt[D1];
        #pragma unroll
        for(int m=0;m<D1;m++) a_nxt[m] = (pload && i<63) ? x1g[(i+1)*D1+m] : 0.f;

        __syncthreads();   // single barrier: z(i) visible; buffers alternate

        // mma phase; B-fragments direct from g_wtf (L1-resident, no prefetch regs)
        const uint32_t* zu = (const uint32_t*)zb;
        const uint32_t* wfi = wfb + (size_t)i*4096;
        #pragma unroll
        for(int s=0;s<8;s++){
            uint32_t afr[2][4];
            #pragma unroll
            for(int mt=0;mt<2;mt++){
                int r0 = mw*32 + mt*16 + g;
                const uint32_t* z0 = zu + r0*68 + s*8 + tid;
                const uint32_t* z1 = zu + (r0+8)*68 + s*8 + tid;
                afr[mt][0]=z0[0]; afr[mt][1]=z1[0]; afr[mt][2]=z0[4]; afr[mt][3]=z1[4];
            }
            #pragma unroll
            for(int nt=0;nt<NT;nt++){
                uint2 bv = *(const uint2*)(wfi + s*512 + nt*64);
                uint32_t bfr[2]; bfr[0]=bv.x; bfr[1]=bv.y;
                #pragma unroll
                for(int mt=0;mt<2;mt++)
                    mma8(acc[mt][nt], afr[mt], bfr);
            }
        }
        #pragma unroll
        for(int m=0;m<D1;m++) a_cur[m]=a_nxt[m];
    }

    // epilogue: registers -> global
    #pragma unroll
    for(int mt=0;mt<2;mt++){
        #pragma unroll
        for(int rr=0;rr<2;rr++){
            int row = mw*32 + mt*16 + g + rr*8;
            if(row >= NBD3) continue;
            int b = row / D3, k = row - (row/D3)*D3;
            if(B0+b >= n) continue;
            float* ob = out + (size_t)(B0+b)*576 + K0 + k;
            #pragma unroll
            for(int nt=0;nt<NT;nt++){
                int o = nw*NS + nt*8 + 2*tid;
                float v0 = acc[mt][nt][rr*2+0];
                float v1 = acc[mt][nt][rr*2+1];
                if(ACC){ ob[o*9]+=v0; ob[(o+1)*9]+=v1; }
                else   { ob[o*9]=v0;  ob[(o+1)*9]=v1;  }
            }
        }
    }
}

// ---------------- launch (size-based operand identification) ----------------
extern "C" void kernel_launch(void* const* d_in, const int* in_sizes, int n_in,
                              void* d_out, int out_size){
    const long long WELEMS=(long long)NPATH*64*64*64;
    const float* w=nullptr;
    long long minOther=0x7fffffffffffLL;
    for(int i=0;i<n_in;i++) if((long long)in_sizes[i]==WELEMS && !w) w=(const float*)d_in[i];
    for(int i=0;i<n_in;i++){ if((const float*)d_in[i]==w) continue;
        if((long long)in_sizes[i]<minOther) minOther=in_sizes[i]; }
    const int nvec=(int)(minOther/64);
    const float* x1p[3]={nullptr,nullptr,nullptr};
    const float* x2p[3]={nullptr,nullptr,nullptr};
    for(int i=0;i<n_in;i++){
        const float* p=(const float*)d_in[i]; if(p==w) continue;
        long long sz=in_sizes[i];
        for(int l=0;l<3;l++) if(sz==(long long)nvec*64*(2*l+1)){
            if(!x1p[l]) x1p[l]=p; else x2p[l]=p; break; }
    }
    float* out=(float*)d_out;

    hctp_build_cg<<<1,32>>>();
    hctp_wprep<<<dim3(64,NPATH),256>>>(w);

#define LP(Pp,L1,L2,L3,NB,TPB,ACC) do{ \
    constexpr int smem=smem_floats(L1,L2,L3,NB)*4; \
    cudaFuncSetAttribute(tp_mma<L1,L2,L3,Pp,NB,TPB,ACC>, cudaFuncAttributeMaxDynamicSharedMemorySize, smem); \
    tp_mma<L1,L2,L3,Pp,NB,TPB,ACC><<<(nvec+NB-1)/NB,256,smem>>>(x1p[L1],x2p[L2],out,nvec); }while(0)

    LP(0, 0,0,0, 48, 4, false);
    LP(1, 0,1,1, 42, 4, false);
    LP(2, 0,2,2, 25, 8, false);
    LP(3, 1,0,1, 42, 4, true);
    LP(4, 1,1,0, 48, 4, true);
    LP(5, 1,1,2, 25, 8, true);
    LP(6, 1,2,1, 42, 4, true);
    LP(7, 2,0,2, 25, 8, true);
    LP(8, 2,1,1, 42, 4, true);
    LP(9, 2,2,0, 48, 4, true);
    LP(10,2,2,2, 25, 8, true);
#undef LP
}